// round 1
// baseline (speedup 1.0000x reference)
#include <cuda_runtime.h>
#include <math.h>

// Shapes (fixed by the problem)
#define PB 16      // batch
#define PP 64      // patches
#define PDe 512    // embed dim
#define PF 128     // relative feature dim
#define PH 8       // heads
#define PHS 64     // head size
#define PDM 512    // d_model
#define PBP 1024   // B*P

// ---------------- scratch (device globals; no runtime allocation) ----------------
__device__ float g_q [PBP * PDM];      // q projection        [bq][h*64+d]
__device__ float g_kb[PBP * PDM];      // k_base = pe @ Wk[:512]
__device__ float g_vb[PBP * PDM];      // v_base = pe @ Wv[:512]
__device__ float g_qk[PBP * PH * PF];  // qk[bq][h][f]
__device__ float g_sb[PB * PH * PP * PP]; // scores_base [b][h][q][p] (unscaled)
__device__ float g_at[PB * PH * PP * PP]; // attn        [b][h][q][p]
__device__ float g_ar[PBP * PH * PF];  // ar[bq][h][f]
__device__ float g_cb[PBP * PDM];      // combined pre-Wo output [bq][h*64+d]

// ---------------- generic 64x64-tile fp32 GEMM body: C[M,512] = A[M,512] @ W[512,512] ----------------
__device__ __forceinline__ void gemm_body(const float* __restrict__ A,
                                          const float* __restrict__ W,
                                          float* __restrict__ C)
{
    __shared__ float As[16][64];
    __shared__ float Bs[16][68];
    const int m0 = blockIdx.y * 64;
    const int n0 = blockIdx.x * 64;
    const int tid = threadIdx.x;
    const int tx = tid & 15, ty = tid >> 4;
    const int ra = tid >> 2, ca = (tid & 3) * 4;   // A-load coords
    const int rb = tid >> 4, cb = (tid & 15) * 4;  // B-load coords
    float acc[4][4] = {};

    for (int k0 = 0; k0 < 512; k0 += 16) {
        float4 va = *(const float4*)(A + (size_t)(m0 + ra) * 512 + k0 + ca);
        float4 vb = *(const float4*)(W + (size_t)(k0 + rb) * 512 + n0 + cb);
        __syncthreads();   // previous compute done before overwriting tiles
        As[ca + 0][ra] = va.x; As[ca + 1][ra] = va.y;
        As[ca + 2][ra] = va.z; As[ca + 3][ra] = va.w;
        *(float4*)&Bs[rb][cb] = vb;
        __syncthreads();
#pragma unroll
        for (int k = 0; k < 16; k++) {
            float a[4], b[4];
            *(float4*)a = *(const float4*)&As[k][ty * 4];
            *(float4*)b = *(const float4*)&Bs[k][tx * 4];
#pragma unroll
            for (int i = 0; i < 4; i++)
#pragma unroll
                for (int j = 0; j < 4; j++)
                    acc[i][j] = fmaf(a[i], b[j], acc[i][j]);
        }
    }
#pragma unroll
    for (int i = 0; i < 4; i++)
        *(float4*)(C + (size_t)(m0 + ty * 4 + i) * 512 + n0 + tx * 4) = *(float4*)acc[i];
}

// K1: q / k_base / v_base projections (blockIdx.z selects which)
__global__ void __launch_bounds__(256) proj_kernel(const float* __restrict__ pe,
                                                   const float* __restrict__ Wq,
                                                   const float* __restrict__ Wk,
                                                   const float* __restrict__ Wv)
{
    const float* W = (blockIdx.z == 0) ? Wq : (blockIdx.z == 1) ? Wk : Wv;
    float* C = (blockIdx.z == 0) ? g_q : (blockIdx.z == 1) ? g_kb : g_vb;
    gemm_body(pe, W, C);
}

// K7: final output projection
__global__ void __launch_bounds__(256) final_kernel(const float* __restrict__ Wo,
                                                    float* __restrict__ out)
{
    gemm_body(g_cb, Wo, out);
}

// K2: qk[bq][h][f] = sum_d q[bq][h*64+d] * Wk[512+f][h*64+d]
// grid (16 m-tiles, 8 heads), 256 threads; f processed in two 64-chunks
__global__ void __launch_bounds__(256) qk_kernel(const float* __restrict__ Wk)
{
    const int h = blockIdx.y;
    const int m0 = blockIdx.x * 64;
    __shared__ float As[64 * 64];   // [m][d]
    __shared__ float Ws[64 * 65];   // [f_local][d], padded
    const int tid = threadIdx.x, tx = tid & 15, ty = tid >> 4;

#pragma unroll
    for (int i = 0; i < 4; i++) {
        int idx = i * 256 + tid;
        int r = idx >> 4, c = (idx & 15) * 4;
        *(float4*)&As[r * 64 + c] =
            *(const float4*)(g_q + (size_t)(m0 + r) * 512 + h * 64 + c);
    }

    for (int fc = 0; fc < 2; fc++) {
        __syncthreads();  // As visible (fc=0) / previous compute done (fc=1)
#pragma unroll
        for (int i = 0; i < 4; i++) {
            int idx = i * 256 + tid;
            int f = idx >> 4, c = (idx & 15) * 4;
            float4 v = *(const float4*)(Wk + (size_t)(512 + fc * 64 + f) * 512 + h * 64 + c);
            Ws[f * 65 + c] = v.x; Ws[f * 65 + c + 1] = v.y;
            Ws[f * 65 + c + 2] = v.z; Ws[f * 65 + c + 3] = v.w;
        }
        __syncthreads();
        float acc[4][4] = {};
#pragma unroll
        for (int d = 0; d < 64; d++) {
            float a[4], w[4];
#pragma unroll
            for (int i = 0; i < 4; i++) a[i] = As[(ty * 4 + i) * 64 + d];
#pragma unroll
            for (int j = 0; j < 4; j++) w[j] = Ws[(tx * 4 + j) * 65 + d];
#pragma unroll
            for (int i = 0; i < 4; i++)
#pragma unroll
                for (int j = 0; j < 4; j++)
                    acc[i][j] = fmaf(a[i], w[j], acc[i][j]);
        }
#pragma unroll
        for (int i = 0; i < 4; i++)
            *(float4*)(g_qk + (size_t)(m0 + ty * 4 + i) * (PH * PF) + h * PF + fc * 64 + tx * 4) =
                *(float4*)acc[i];
    }
}

// K3: scores_base[b][h][q][p] = sum_d q[bq][hd] * k_base[bp][hd]   (unscaled)
__global__ void __launch_bounds__(256) sbase_kernel()
{
    const int b = blockIdx.x, h = blockIdx.y;
    __shared__ float Qs[64 * 65];
    __shared__ float Ks[64 * 65];
    const int tid = threadIdx.x, tx = tid & 15, ty = tid >> 4;

#pragma unroll
    for (int i = 0; i < 4; i++) {
        int idx = i * 256 + tid;
        int r = idx >> 4, c = (idx & 15) * 4;
        float4 vq = *(const float4*)(g_q  + (size_t)(b * 64 + r) * 512 + h * 64 + c);
        float4 vk = *(const float4*)(g_kb + (size_t)(b * 64 + r) * 512 + h * 64 + c);
        Qs[r * 65 + c] = vq.x; Qs[r * 65 + c + 1] = vq.y;
        Qs[r * 65 + c + 2] = vq.z; Qs[r * 65 + c + 3] = vq.w;
        Ks[r * 65 + c] = vk.x; Ks[r * 65 + c + 1] = vk.y;
        Ks[r * 65 + c + 2] = vk.z; Ks[r * 65 + c + 3] = vk.w;
    }
    __syncthreads();

    float acc[4][4] = {};
#pragma unroll
    for (int d = 0; d < 64; d++) {
        float qv[4], kv[4];
#pragma unroll
        for (int i = 0; i < 4; i++) qv[i] = Qs[(ty * 4 + i) * 65 + d];
#pragma unroll
        for (int j = 0; j < 4; j++) kv[j] = Ks[(tx * 4 + j) * 65 + d];
#pragma unroll
        for (int i = 0; i < 4; i++)
#pragma unroll
            for (int j = 0; j < 4; j++)
                acc[i][j] = fmaf(qv[i], kv[j], acc[i][j]);
    }
    float* out = g_sb + (size_t)((b * 8 + h) * 64) * 64;
#pragma unroll
    for (int i = 0; i < 4; i++)
        *(float4*)(out + (ty * 4 + i) * 64 + tx * 4) = *(float4*)acc[i];
}

// K4: per-(b,q) fused kernel: rf tile in smem (read once), scores_rel, softmax, ar
__global__ void __launch_bounds__(256) attn_kernel(const float* __restrict__ rf)
{
    const int bq = blockIdx.x;
    const int b = bq >> 6, q = bq & 63;
    __shared__ float rf_s[64 * 132];  // [p][f], pad 132 (33 float4): conflict-free f4 access
    __shared__ float qk_s[8 * 132];   // [h][f]
    __shared__ float s_s [8 * 64];    // scores
    __shared__ float at_s[8 * 68];    // attn
    const int tid = threadIdx.x;

    // load rf tile: 8192 floats = 2048 float4
    const float4* rfg = (const float4*)(rf + (size_t)bq * 64 * 128);
    float4* rf4 = (float4*)rf_s;
#pragma unroll
    for (int i = 0; i < 8; i++) {
        int idx = i * 256 + tid;
        int p = idx >> 5, f4 = idx & 31;
        rf4[p * 33 + f4] = rfg[idx];
    }
    // load qk[bq]: 1024 floats = 256 float4
    {
        const float4* qkg = (const float4*)(g_qk + (size_t)bq * (PH * PF));
        int h = tid >> 5, f4 = tid & 31;
        ((float4*)qk_s)[h * 33 + f4] = qkg[tid];
    }
    __syncthreads();

    // scores: s[h][p] = 0.125*(sbase + sum_f qk[h][f]*rf[p][f])
#pragma unroll
    for (int rep = 0; rep < 2; rep++) {
        int o = rep * 256 + tid;
        int h = o >> 6, p = o & 63;
        const float4* qr = (const float4*)qk_s + h * 33;
        const float4* rr = rf4 + p * 33;
        float acc = 0.f;
#pragma unroll
        for (int f4 = 0; f4 < 32; f4++) {
            float4 a = qr[f4], r = rr[f4];
            acc = fmaf(a.x, r.x, acc); acc = fmaf(a.y, r.y, acc);
            acc = fmaf(a.z, r.z, acc); acc = fmaf(a.w, r.w, acc);
        }
        float sb = g_sb[(size_t)((b * 8 + h) * 64 + q) * 64 + p];
        s_s[h * 64 + p] = 0.125f * (acc + sb);
    }
    __syncthreads();

    // softmax: warp w -> head w (64 values, 2 per lane)
    {
        int w = tid >> 5, l = tid & 31;
        float v0 = s_s[w * 64 + l], v1 = s_s[w * 64 + 32 + l];
        float m = fmaxf(v0, v1);
#pragma unroll
        for (int off = 16; off; off >>= 1) m = fmaxf(m, __shfl_xor_sync(0xffffffffu, m, off));
        float e0 = __expf(v0 - m), e1 = __expf(v1 - m);
        float s = e0 + e1;
#pragma unroll
        for (int off = 16; off; off >>= 1) s += __shfl_xor_sync(0xffffffffu, s, off);
        float inv = 1.f / s;
        float a0 = e0 * inv, a1 = e1 * inv;
        at_s[w * 68 + l] = a0; at_s[w * 68 + 32 + l] = a1;
        float* ag = g_at + (size_t)((b * 8 + w) * 64 + q) * 64;
        ag[l] = a0; ag[32 + l] = a1;
    }
    __syncthreads();

    // ar[h][f] = sum_p attn[h][p] * rf[p][f]   (thread -> (h, f4))
    {
        int h = tid >> 5, f4 = tid & 31;
        const float* ah = at_s + h * 68;
        float4 acc = make_float4(0.f, 0.f, 0.f, 0.f);
#pragma unroll
        for (int p = 0; p < 64; p++) {
            float a = ah[p];
            float4 r = rf4[p * 33 + f4];
            acc.x = fmaf(a, r.x, acc.x); acc.y = fmaf(a, r.y, acc.y);
            acc.z = fmaf(a, r.z, acc.z); acc.w = fmaf(a, r.w, acc.w);
        }
        ((float4*)(g_ar + (size_t)bq * (PH * PF)))[tid] = acc;
    }
}

// K5: out_rel[m][h*64+d] = sum_f ar[m][h][f] * Wv[512+f][h*64+d]  -> write g_cb
__global__ void __launch_bounds__(256) outrel_kernel(const float* __restrict__ Wv)
{
    const int h = blockIdx.y;
    const int m0 = blockIdx.x * 64;
    __shared__ float As[64 * 68];  // [m][f_local]
    __shared__ float Bs[64 * 68];  // [f_local][d]
    const int tid = threadIdx.x, tx = tid & 15, ty = tid >> 4;
    float acc[4][4] = {};

    for (int fc = 0; fc < 2; fc++) {
        __syncthreads();
#pragma unroll
        for (int i = 0; i < 4; i++) {
            int idx = i * 256 + tid;
            int r = idx >> 4, c4 = idx & 15;
            ((float4*)As)[r * 17 + c4] =
                *(const float4*)(g_ar + (size_t)(m0 + r) * (PH * PF) + h * PF + fc * 64 + c4 * 4);
            ((float4*)Bs)[r * 17 + c4] =
                *(const float4*)(Wv + (size_t)(512 + fc * 64 + r) * 512 + h * 64 + c4 * 4);
        }
        __syncthreads();
#pragma unroll
        for (int f = 0; f < 64; f++) {
            float a[4], bv[4];
#pragma unroll
            for (int i = 0; i < 4; i++) a[i] = As[(ty * 4 + i) * 68 + f];
#pragma unroll
            for (int j = 0; j < 4; j++) bv[j] = Bs[f * 68 + tx * 4 + j];
#pragma unroll
            for (int i = 0; i < 4; i++)
#pragma unroll
                for (int j = 0; j < 4; j++)
                    acc[i][j] = fmaf(a[i], bv[j], acc[i][j]);
        }
    }
#pragma unroll
    for (int i = 0; i < 4; i++)
        *(float4*)(g_cb + (size_t)(m0 + ty * 4 + i) * 512 + h * 64 + tx * 4) = *(float4*)acc[i];
}

// K6: out_base[b][h][q][d] = sum_p attn[b][h][q][p] * v_base[b][p][h][d]; accumulate into g_cb
__global__ void __launch_bounds__(256) outbase_kernel()
{
    const int b = blockIdx.x, h = blockIdx.y;
    __shared__ float At[64 * 68];  // [q][p]
    __shared__ float Vs[64 * 68];  // [p][d]
    const int tid = threadIdx.x, tx = tid & 15, ty = tid >> 4;

#pragma unroll
    for (int i = 0; i < 4; i++) {
        int idx = i * 256 + tid;
        int r = idx >> 4, c4 = idx & 15;
        ((float4*)At)[r * 17 + c4] =
            *(const float4*)(g_at + (size_t)((b * 8 + h) * 64 + r) * 64 + c4 * 4);
        ((float4*)Vs)[r * 17 + c4] =
            *(const float4*)(g_vb + (size_t)(b * 64 + r) * 512 + h * 64 + c4 * 4);
    }
    __syncthreads();

    float acc[4][4] = {};
#pragma unroll
    for (int p = 0; p < 64; p++) {
        float av[4], vv[4];
#pragma unroll
        for (int i = 0; i < 4; i++) av[i] = At[(ty * 4 + i) * 68 + p];
#pragma unroll
        for (int j = 0; j < 4; j++) vv[j] = Vs[p * 68 + tx * 4 + j];
#pragma unroll
        for (int i = 0; i < 4; i++)
#pragma unroll
            for (int j = 0; j < 4; j++)
                acc[i][j] = fmaf(av[i], vv[j], acc[i][j]);
    }
#pragma unroll
    for (int i = 0; i < 4; i++) {
        float* cp = g_cb + (size_t)(b * 64 + ty * 4 + i) * 512 + h * 64 + tx * 4;
        float4 old = *(float4*)cp;
        old.x += acc[i][0]; old.y += acc[i][1]; old.z += acc[i][2]; old.w += acc[i][3];
        *(float4*)cp = old;
    }
}

extern "C" void kernel_launch(void* const* d_in, const int* in_sizes, int n_in,
                              void* d_out, int out_size)
{
    (void)in_sizes; (void)n_in; (void)out_size;
    const float* pe = (const float*)d_in[0];  // [16,64,512]
    const float* rf = (const float*)d_in[1];  // [16,64,64,128]
    // d_in[2] is the mask: all-ones and unused by the reference math
    const float* Wq = (const float*)d_in[3];  // [512,512]
    const float* Wk = (const float*)d_in[4];  // [640,512]
    const float* Wv = (const float*)d_in[5];  // [640,512]
    const float* Wo = (const float*)d_in[6];  // [512,512]
    float* out = (float*)d_out;               // [16,64,512]

    dim3 t(256);
    proj_kernel  <<<dim3(8, 16, 3), t>>>(pe, Wq, Wk, Wv);
    qk_kernel    <<<dim3(16, 8),    t>>>(Wk);
    sbase_kernel <<<dim3(16, 8),    t>>>();
    attn_kernel  <<<dim3(1024),     t>>>(rf);
    outrel_kernel<<<dim3(16, 8),    t>>>(Wv);
    outbase_kernel<<<dim3(16, 8),   t>>>();
    final_kernel <<<dim3(8, 16),    t>>>(Wo, out);
}

// round 2
// speedup vs baseline: 1.0528x; 1.0528x over previous
#include <cuda_runtime.h>
#include <math.h>

#define PB 16
#define PP 64
#define PDe 512
#define PF 128
#define PH 8
#define PHS 64
#define PDM 512
#define PBP 1024

typedef unsigned long long u64;

// ---------------- packed f32x2 helpers (FFMA2 — 2x fp32 throughput) ----------------
__device__ __forceinline__ u64 pack_dup(float x) {
    u64 r; asm("mov.b64 %0, {%1, %1};" : "=l"(r) : "f"(x)); return r;
}
__device__ __forceinline__ void ffma2(u64& d, u64 a, u64 b) {
    asm("fma.rn.f32x2 %0, %1, %2, %3;" : "=l"(d) : "l"(a), "l"(b), "l"(d));
}
__device__ __forceinline__ void unpack2(float& lo, float& hi, u64 v) {
    asm("mov.b64 {%0, %1}, %2;" : "=f"(lo), "=f"(hi) : "l"(v));
}

// ---------------- scratch ----------------
__device__ float g_q [PBP * PDM];
__device__ float g_kb[PBP * PDM];
__device__ float g_vb[PBP * PDM];
__device__ float g_qk[PBP * PH * PF];
__device__ float g_sb[PB * PH * PP * PP];
__device__ float g_at[PB * PH * PP * PP];
__device__ float g_ar[PBP * PH * PF];
__device__ float g_cb[PBP * PDM];

// ---------------- 64x64-tile fp32 GEMM, K=512, double-buffered, FFMA2 ----------------
// C[m0:m0+64, n0:n0+64] = A[m0:, 0:512] @ W[0:512, n0:]
__device__ __forceinline__ void gemm64_body(const float* __restrict__ A,
                                            const float* __restrict__ W,
                                            float* __restrict__ C,
                                            int m0, int n0)
{
    __shared__ float As[2][16][64];   // [buf][k][m]  (k-major)
    __shared__ float Bs[2][16][64];   // [buf][k][n]
    const int tid = threadIdx.x;
    const int tx = tid & 15, ty = tid >> 4;
    const int ar = tid >> 2, ac4 = tid & 3;       // A: row, k-chunk(float4)
    const int br = tid >> 4, bc = (tid & 15) * 4; // B: k-row, col

    ulonglong2 acc[4];
#pragma unroll
    for (int i = 0; i < 4; i++) acc[i] = make_ulonglong2(0ull, 0ull);

    // prologue: ktile 0
    {
        float4 va = *(const float4*)(A + (size_t)(m0 + ar) * 512 + ac4 * 4);
        float4 vb = *(const float4*)(W + (size_t)br * 512 + n0 + bc);
        As[0][ac4 * 4 + 0][ar] = va.x; As[0][ac4 * 4 + 1][ar] = va.y;
        As[0][ac4 * 4 + 2][ar] = va.z; As[0][ac4 * 4 + 3][ar] = va.w;
        *(float4*)&Bs[0][br][bc] = vb;
    }
    __syncthreads();

    int buf = 0;
    for (int kt = 0; kt < 32; kt++) {
        float4 na, nb;
        if (kt < 31) {
            int k0 = (kt + 1) * 16;
            na = *(const float4*)(A + (size_t)(m0 + ar) * 512 + k0 + ac4 * 4);
            nb = *(const float4*)(W + (size_t)(k0 + br) * 512 + n0 + bc);
        }
#pragma unroll
        for (int k = 0; k < 16; k++) {
            float4 a4 = *(const float4*)&As[buf][k][ty * 4];
            float4 b4 = *(const float4*)&Bs[buf][k][tx * 4];
            u64 bp0 = *(u64*)&b4.x, bp1 = *(u64*)&b4.z;
            u64 a0 = pack_dup(a4.x), a1 = pack_dup(a4.y);
            u64 a2 = pack_dup(a4.z), a3 = pack_dup(a4.w);
            ffma2(acc[0].x, a0, bp0); ffma2(acc[0].y, a0, bp1);
            ffma2(acc[1].x, a1, bp0); ffma2(acc[1].y, a1, bp1);
            ffma2(acc[2].x, a2, bp0); ffma2(acc[2].y, a2, bp1);
            ffma2(acc[3].x, a3, bp0); ffma2(acc[3].y, a3, bp1);
        }
        if (kt < 31) {
            As[buf ^ 1][ac4 * 4 + 0][ar] = na.x; As[buf ^ 1][ac4 * 4 + 1][ar] = na.y;
            As[buf ^ 1][ac4 * 4 + 2][ar] = na.z; As[buf ^ 1][ac4 * 4 + 3][ar] = na.w;
            *(float4*)&Bs[buf ^ 1][br][bc] = nb;
            __syncthreads();
            buf ^= 1;
        }
    }
#pragma unroll
    for (int i = 0; i < 4; i++)
        *(float4*)(C + (size_t)(m0 + ty * 4 + i) * 512 + n0 + tx * 4) = *(float4*)&acc[i];
}

// K1: projections
__global__ void __launch_bounds__(256) proj_kernel(const float* __restrict__ pe,
                                                   const float* __restrict__ Wq,
                                                   const float* __restrict__ Wk,
                                                   const float* __restrict__ Wv)
{
    const float* W = (blockIdx.z == 0) ? Wq : (blockIdx.z == 1) ? Wk : Wv;
    float* C = (blockIdx.z == 0) ? g_q : (blockIdx.z == 1) ? g_kb : g_vb;
    gemm64_body(pe, W, C, blockIdx.y * 64, blockIdx.x * 64);
}

// K7: final projection
__global__ void __launch_bounds__(256) final_kernel(const float* __restrict__ Wo,
                                                    float* __restrict__ out)
{
    gemm64_body(g_cb, Wo, out, blockIdx.y * 64, blockIdx.x * 64);
}

// K2: qk[m][h][f] = sum_d q[m][h*64+d] * Wk[512+f][h*64+d]
__global__ void __launch_bounds__(256) qk_kernel(const float* __restrict__ Wk)
{
    const int h = blockIdx.y;
    const int m0 = blockIdx.x * 64;
    __shared__ float Qt[64 * 68];   // [d][m]
    __shared__ float Wt[64 * 68];   // [d][f_local]
    const int tid = threadIdx.x, tx = tid & 15, ty = tid >> 4;
    const int lr = tid >> 4, lc4 = tid & 15;

#pragma unroll
    for (int i = 0; i < 4; i++) {
        int r = i * 16 + lr;
        float4 v = *(const float4*)(g_q + (size_t)(m0 + r) * 512 + h * 64 + lc4 * 4);
        Qt[(lc4 * 4 + 0) * 68 + r] = v.x; Qt[(lc4 * 4 + 1) * 68 + r] = v.y;
        Qt[(lc4 * 4 + 2) * 68 + r] = v.z; Qt[(lc4 * 4 + 3) * 68 + r] = v.w;
    }
    for (int fc = 0; fc < 2; fc++) {
        __syncthreads();
#pragma unroll
        for (int i = 0; i < 4; i++) {
            int f = i * 16 + lr;
            float4 v = *(const float4*)(Wk + (size_t)(512 + fc * 64 + f) * 512 + h * 64 + lc4 * 4);
            Wt[(lc4 * 4 + 0) * 68 + f] = v.x; Wt[(lc4 * 4 + 1) * 68 + f] = v.y;
            Wt[(lc4 * 4 + 2) * 68 + f] = v.z; Wt[(lc4 * 4 + 3) * 68 + f] = v.w;
        }
        __syncthreads();
        ulonglong2 acc[4];
#pragma unroll
        for (int i = 0; i < 4; i++) acc[i] = make_ulonglong2(0ull, 0ull);
#pragma unroll
        for (int d = 0; d < 64; d++) {
            float4 a4 = *(const float4*)&Qt[d * 68 + ty * 4];
            float4 b4 = *(const float4*)&Wt[d * 68 + tx * 4];
            u64 bp0 = *(u64*)&b4.x, bp1 = *(u64*)&b4.z;
            u64 a0 = pack_dup(a4.x), a1 = pack_dup(a4.y);
            u64 a2 = pack_dup(a4.z), a3 = pack_dup(a4.w);
            ffma2(acc[0].x, a0, bp0); ffma2(acc[0].y, a0, bp1);
            ffma2(acc[1].x, a1, bp0); ffma2(acc[1].y, a1, bp1);
            ffma2(acc[2].x, a2, bp0); ffma2(acc[2].y, a2, bp1);
            ffma2(acc[3].x, a3, bp0); ffma2(acc[3].y, a3, bp1);
        }
#pragma unroll
        for (int i = 0; i < 4; i++)
            *(float4*)(g_qk + (size_t)(m0 + ty * 4 + i) * (PH * PF) + h * PF + fc * 64 + tx * 4) =
                *(float4*)&acc[i];
    }
}

// K3: scores_base[b][h][q][p] (unscaled)
__global__ void __launch_bounds__(256) sbase_kernel()
{
    const int b = blockIdx.x, h = blockIdx.y;
    __shared__ float Qt[64 * 68];   // [d][q]
    __shared__ float Kt[64 * 68];   // [d][p]
    const int tid = threadIdx.x, tx = tid & 15, ty = tid >> 4;
    const int lr = tid >> 4, lc4 = tid & 15;

#pragma unroll
    for (int i = 0; i < 4; i++) {
        int r = i * 16 + lr;
        float4 vq = *(const float4*)(g_q  + (size_t)(b * 64 + r) * 512 + h * 64 + lc4 * 4);
        float4 vk = *(const float4*)(g_kb + (size_t)(b * 64 + r) * 512 + h * 64 + lc4 * 4);
        Qt[(lc4 * 4 + 0) * 68 + r] = vq.x; Qt[(lc4 * 4 + 1) * 68 + r] = vq.y;
        Qt[(lc4 * 4 + 2) * 68 + r] = vq.z; Qt[(lc4 * 4 + 3) * 68 + r] = vq.w;
        Kt[(lc4 * 4 + 0) * 68 + r] = vk.x; Kt[(lc4 * 4 + 1) * 68 + r] = vk.y;
        Kt[(lc4 * 4 + 2) * 68 + r] = vk.z; Kt[(lc4 * 4 + 3) * 68 + r] = vk.w;
    }
    __syncthreads();

    ulonglong2 acc[4];
#pragma unroll
    for (int i = 0; i < 4; i++) acc[i] = make_ulonglong2(0ull, 0ull);
#pragma unroll
    for (int d = 0; d < 64; d++) {
        float4 a4 = *(const float4*)&Qt[d * 68 + ty * 4];
        float4 b4 = *(const float4*)&Kt[d * 68 + tx * 4];
        u64 bp0 = *(u64*)&b4.x, bp1 = *(u64*)&b4.z;
        u64 a0 = pack_dup(a4.x), a1 = pack_dup(a4.y);
        u64 a2 = pack_dup(a4.z), a3 = pack_dup(a4.w);
        ffma2(acc[0].x, a0, bp0); ffma2(acc[0].y, a0, bp1);
        ffma2(acc[1].x, a1, bp0); ffma2(acc[1].y, a1, bp1);
        ffma2(acc[2].x, a2, bp0); ffma2(acc[2].y, a2, bp1);
        ffma2(acc[3].x, a3, bp0); ffma2(acc[3].y, a3, bp1);
    }
    float* out = g_sb + (size_t)((b * 8 + h) * 64) * 64;
#pragma unroll
    for (int i = 0; i < 4; i++)
        *(float4*)(out + (ty * 4 + i) * 64 + tx * 4) = *(float4*)&acc[i];
}

// K4: fused per-(b,q): scores_rel + softmax + ar, rf read once. 3 blocks/SM target.
__global__ void __launch_bounds__(256, 3) attn_kernel(const float* __restrict__ rf)
{
    const int bq = blockIdx.x;
    const int b = bq >> 6, q = bq & 63;
    __shared__ float rf_s[64 * 132];
    __shared__ float qk_s[8 * 132];
    __shared__ float s_s [8 * 64];
    __shared__ float at_s[8 * 68];
    const int tid = threadIdx.x;

    const float4* rfg = (const float4*)(rf + (size_t)bq * 8192);
    float4* rf4 = (float4*)rf_s;
#pragma unroll
    for (int i = 0; i < 8; i++) {
        int idx = i * 256 + tid;
        rf4[(idx >> 5) * 33 + (idx & 31)] = rfg[idx];
    }
    ((float4*)qk_s)[(tid >> 5) * 33 + (tid & 31)] =
        ((const float4*)(g_qk + (size_t)bq * (PH * PF)))[tid];
    __syncthreads();

    // scores: s[h][p] = 0.125*(sbase + qk[h]·rf[p])
#pragma unroll
    for (int rep = 0; rep < 2; rep++) {
        int o = rep * 256 + tid;
        int h = o >> 6, p = o & 63;
        const float4* qr = (const float4*)qk_s + h * 33;
        const float4* rr = rf4 + p * 33;
        u64 acc2 = 0ull;
#pragma unroll 8
        for (int f4 = 0; f4 < 32; f4++) {
            float4 a = qr[f4], r = rr[f4];
            ffma2(acc2, *(u64*)&a.x, *(u64*)&r.x);
            ffma2(acc2, *(u64*)&a.z, *(u64*)&r.z);
        }
        float lo, hi; unpack2(lo, hi, acc2);
        float sb = g_sb[(size_t)((b * 8 + h) * 64 + q) * 64 + p];
        s_s[h * 64 + p] = 0.125f * (lo + hi + sb);
    }
    __syncthreads();

    // softmax: warp w -> head w
    {
        int w = tid >> 5, l = tid & 31;
        float v0 = s_s[w * 64 + l], v1 = s_s[w * 64 + 32 + l];
        float m = fmaxf(v0, v1);
#pragma unroll
        for (int off = 16; off; off >>= 1) m = fmaxf(m, __shfl_xor_sync(0xffffffffu, m, off));
        float e0 = __expf(v0 - m), e1 = __expf(v1 - m);
        float s = e0 + e1;
#pragma unroll
        for (int off = 16; off; off >>= 1) s += __shfl_xor_sync(0xffffffffu, s, off);
        float inv = 1.f / s;
        float a0 = e0 * inv, a1 = e1 * inv;
        at_s[w * 68 + l] = a0; at_s[w * 68 + 32 + l] = a1;
        float* ag = g_at + (size_t)((b * 8 + w) * 64 + q) * 64;
        ag[l] = a0; ag[32 + l] = a1;
    }
    __syncthreads();

    // ar[h][f] = attn[h]·rf[:,f]
    {
        int h = tid >> 5, f4 = tid & 31;
        const float* ah = at_s + h * 68;
        ulonglong2 acc = make_ulonglong2(0ull, 0ull);
#pragma unroll 8
        for (int p = 0; p < 64; p++) {
            u64 ad = pack_dup(ah[p]);
            float4 r = rf4[p * 33 + f4];
            ffma2(acc.x, ad, *(u64*)&r.x);
            ffma2(acc.y, ad, *(u64*)&r.z);
        }
        ((float4*)(g_ar + (size_t)bq * (PH * PF)))[tid] = *(float4*)&acc;
    }
}

// K5: out_rel -> g_cb
__global__ void __launch_bounds__(256) outrel_kernel(const float* __restrict__ Wv)
{
    const int h = blockIdx.y;
    const int m0 = blockIdx.x * 64;
    __shared__ float At[64 * 68];  // [f_local][m]
    __shared__ float Bs[64 * 68];  // [f_local][d]
    const int tid = threadIdx.x, tx = tid & 15, ty = tid >> 4;
    const int lr = tid >> 4, lc4 = tid & 15;
    ulonglong2 acc[4];
#pragma unroll
    for (int i = 0; i < 4; i++) acc[i] = make_ulonglong2(0ull, 0ull);

    for (int fc = 0; fc < 2; fc++) {
        __syncthreads();
#pragma unroll
        for (int i = 0; i < 4; i++) {
            int r = i * 16 + lr;
            float4 va = *(const float4*)(g_ar + (size_t)(m0 + r) * (PH * PF) + h * PF + fc * 64 + lc4 * 4);
            At[(lc4 * 4 + 0) * 68 + r] = va.x; At[(lc4 * 4 + 1) * 68 + r] = va.y;
            At[(lc4 * 4 + 2) * 68 + r] = va.z; At[(lc4 * 4 + 3) * 68 + r] = va.w;
            *(float4*)&Bs[r * 68 + lc4 * 4] =
                *(const float4*)(Wv + (size_t)(512 + fc * 64 + r) * 512 + h * 64 + lc4 * 4);
        }
        __syncthreads();
#pragma unroll
        for (int f = 0; f < 64; f++) {
            float4 a4 = *(const float4*)&At[f * 68 + ty * 4];
            float4 b4 = *(const float4*)&Bs[f * 68 + tx * 4];
            u64 bp0 = *(u64*)&b4.x, bp1 = *(u64*)&b4.z;
            u64 a0 = pack_dup(a4.x), a1 = pack_dup(a4.y);
            u64 a2 = pack_dup(a4.z), a3 = pack_dup(a4.w);
            ffma2(acc[0].x, a0, bp0); ffma2(acc[0].y, a0, bp1);
            ffma2(acc[1].x, a1, bp0); ffma2(acc[1].y, a1, bp1);
            ffma2(acc[2].x, a2, bp0); ffma2(acc[2].y, a2, bp1);
            ffma2(acc[3].x, a3, bp0); ffma2(acc[3].y, a3, bp1);
        }
    }
#pragma unroll
    for (int i = 0; i < 4; i++)
        *(float4*)(g_cb + (size_t)(m0 + ty * 4 + i) * 512 + h * 64 + tx * 4) = *(float4*)&acc[i];
}

// K6: out_base accumulate into g_cb
__global__ void __launch_bounds__(256) outbase_kernel()
{
    const int b = blockIdx.x, h = blockIdx.y;
    __shared__ float At[64 * 68];  // [p][q]
    __shared__ float Vs[64 * 68];  // [p][d]
    const int tid = threadIdx.x, tx = tid & 15, ty = tid >> 4;
    const int lr = tid >> 4, lc4 = tid & 15;

#pragma unroll
    for (int i = 0; i < 4; i++) {
        int r = i * 16 + lr;
        float4 va = *(const float4*)(g_at + (size_t)((b * 8 + h) * 64 + r) * 64 + lc4 * 4);
        At[(lc4 * 4 + 0) * 68 + r] = va.x; At[(lc4 * 4 + 1) * 68 + r] = va.y;
        At[(lc4 * 4 + 2) * 68 + r] = va.z; At[(lc4 * 4 + 3) * 68 + r] = va.w;
        *(float4*)&Vs[r * 68 + lc4 * 4] =
            *(const float4*)(g_vb + (size_t)(b * 64 + r) * 512 + h * 64 + lc4 * 4);
    }
    __syncthreads();

    ulonglong2 acc[4];
#pragma unroll
    for (int i = 0; i < 4; i++) acc[i] = make_ulonglong2(0ull, 0ull);
#pragma unroll
    for (int p = 0; p < 64; p++) {
        float4 a4 = *(const float4*)&At[p * 68 + ty * 4];
        float4 b4 = *(const float4*)&Vs[p * 68 + tx * 4];
        u64 bp0 = *(u64*)&b4.x, bp1 = *(u64*)&b4.z;
        u64 a0 = pack_dup(a4.x), a1 = pack_dup(a4.y);
        u64 a2 = pack_dup(a4.z), a3 = pack_dup(a4.w);
        ffma2(acc[0].x, a0, bp0); ffma2(acc[0].y, a0, bp1);
        ffma2(acc[1].x, a1, bp0); ffma2(acc[1].y, a1, bp1);
        ffma2(acc[2].x, a2, bp0); ffma2(acc[2].y, a2, bp1);
        ffma2(acc[3].x, a3, bp0); ffma2(acc[3].y, a3, bp1);
    }
#pragma unroll
    for (int i = 0; i < 4; i++) {
        float* cp = g_cb + (size_t)(b * 64 + ty * 4 + i) * 512 + h * 64 + tx * 4;
        float4 old = *(float4*)cp;
        float4 av = *(float4*)&acc[i];
        old.x += av.x; old.y += av.y; old.z += av.z; old.w += av.w;
        *(float4*)cp = old;
    }
}

extern "C" void kernel_launch(void* const* d_in, const int* in_sizes, int n_in,
                              void* d_out, int out_size)
{
    (void)in_sizes; (void)n_in; (void)out_size;
    const float* pe = (const float*)d_in[0];
    const float* rf = (const float*)d_in[1];
    const float* Wq = (const float*)d_in[3];
    const float* Wk = (const float*)d_in[4];
    const float* Wv = (const float*)d_in[5];
    const float* Wo = (const float*)d_in[6];
    float* out = (float*)d_out;

    dim3 t(256);
    proj_kernel   <<<dim3(8, 16, 3), t>>>(pe, Wq, Wk, Wv);
    qk_kernel     <<<dim3(16, 8),    t>>>(Wk);
    sbase_kernel  <<<dim3(16, 8),    t>>>();
    attn_kernel   <<<dim3(1024),     t>>>(rf);
    outrel_kernel <<<dim3(16, 8),    t>>>(Wv);
    outbase_kernel<<<dim3(16, 8),    t>>>();
    final_kernel  <<<dim3(8, 16),    t>>>(Wo, out);
}